// round 3
// baseline (speedup 1.0000x reference)
#include <cuda_runtime.h>
#include <cstddef>

// Problem constants
#define Bn 4
#define Sn 4096
#define Hn 512
#define NEG_INF (-1e7f)

#define BLK 64
#define BKK 16

// Single consolidated scratch region (allocation forbidden -> __device__ global).
// Layout: [Q (B*S*H)] [K (B*S*H)] [V (B*S*H)] [W fallback (B*S*S)]
#define QKV_ELEMS ((size_t)Bn * Sn * Hn)          // 8388608 each
#define W_ELEMS   ((size_t)Bn * Sn * Sn)          // 67108864
__device__ float g_scratch[3 * QKV_ELEMS + W_ELEMS];

__device__ __forceinline__ float* scratch_Q() { return g_scratch; }
__device__ __forceinline__ float* scratch_K() { return g_scratch + QKV_ELEMS; }
__device__ __forceinline__ float* scratch_V() { return g_scratch + 2 * QKV_ELEMS; }
__device__ __forceinline__ float* scratch_W() { return g_scratch + 3 * QKV_ELEMS; }

// ---------------------------------------------------------------------------
// Projection GEMM: C[m,n] = sum_k A[m,k] * W[n,k] + bias[n]
// A: (M,K) row-major, W: (N,K) row-major (nn.Linear weight) -> NT GEMM.
// dst_sel: 0 -> Q, 1 -> K, 2 -> V
// ---------------------------------------------------------------------------
__global__ __launch_bounds__(256) void proj_kernel(
    const float* __restrict__ A, const float* __restrict__ W,
    const float* __restrict__ bias, int dst_sel)
{
    float* __restrict__ C =
        (dst_sel == 0) ? scratch_Q() : (dst_sel == 1) ? scratch_K() : scratch_V();
    const int K = Hn, N = Hn;

    __shared__ float As[BKK][BLK];
    __shared__ float Bs[BKK][BLK];
    const int tid = threadIdx.x;
    const int tx = tid & 15, ty = tid >> 4;
    const int m0 = blockIdx.y * BLK, n0 = blockIdx.x * BLK;
    const int lr = tid >> 2;             // 0..63
    const int lc = (tid & 3) << 2;       // 0,4,8,12

    float acc[4][4] = {};
    for (int k0 = 0; k0 < K; k0 += BKK) {
        float4 a = *(const float4*)(A + (size_t)(m0 + lr) * K + k0 + lc);
        float4 b = *(const float4*)(W + (size_t)(n0 + lr) * K + k0 + lc);
        As[lc + 0][lr] = a.x; As[lc + 1][lr] = a.y; As[lc + 2][lr] = a.z; As[lc + 3][lr] = a.w;
        Bs[lc + 0][lr] = b.x; Bs[lc + 1][lr] = b.y; Bs[lc + 2][lr] = b.z; Bs[lc + 3][lr] = b.w;
        __syncthreads();
        #pragma unroll
        for (int kk = 0; kk < BKK; kk++) {
            float4 av = *(const float4*)&As[kk][ty << 2];
            float4 bv = *(const float4*)&Bs[kk][tx << 2];
            float am[4] = {av.x, av.y, av.z, av.w};
            float bn[4] = {bv.x, bv.y, bv.z, bv.w};
            #pragma unroll
            for (int i = 0; i < 4; i++)
                #pragma unroll
                for (int j = 0; j < 4; j++)
                    acc[i][j] += am[i] * bn[j];
        }
        __syncthreads();
    }
    const int nb = n0 + (tx << 2);
    float4 bb = *(const float4*)(bias + nb);
    #pragma unroll
    for (int i = 0; i < 4; i++) {
        int m = m0 + (ty << 2) + i;
        float4 out;
        out.x = acc[i][0] + bb.x;
        out.y = acc[i][1] + bb.y;
        out.z = acc[i][2] + bb.z;
        out.w = acc[i][3] + bb.w;
        *(float4*)(C + (size_t)m * N + nb) = out;
    }
}

// ---------------------------------------------------------------------------
// Scores: Wout[b,i,j] = scale * sum_h Q[b,i,h] K[b,j,h]; NEG_INF where j>i.
// Fully-masked tiles (j0 > i0+63) are skipped (softmax writes their zeros).
// use_fallback != 0 -> scores go to the device scratch instead of wts.
// ---------------------------------------------------------------------------
__global__ __launch_bounds__(256) void scores_kernel(
    float* wts, int use_fallback, float scale)
{
    const int b = blockIdx.z;
    const int i0 = blockIdx.y * BLK;
    const int j0 = blockIdx.x * BLK;
    if (j0 > i0 + BLK - 1) return;  // fully above diagonal

    float* __restrict__ Wout = use_fallback ? scratch_W() : wts;
    const float* A  = scratch_Q() + (size_t)b * Sn * Hn;
    const float* Bm = scratch_K() + (size_t)b * Sn * Hn;
    float* Out = Wout + (size_t)b * Sn * Sn;

    __shared__ float As[BKK][BLK];
    __shared__ float Bs[BKK][BLK];
    const int tid = threadIdx.x;
    const int tx = tid & 15, ty = tid >> 4;
    const int lr = tid >> 2;
    const int lc = (tid & 3) << 2;

    float acc[4][4] = {};
    for (int k0 = 0; k0 < Hn; k0 += BKK) {
        float4 a  = *(const float4*)(A  + (size_t)(i0 + lr) * Hn + k0 + lc);
        float4 b4 = *(const float4*)(Bm + (size_t)(j0 + lr) * Hn + k0 + lc);
        As[lc + 0][lr] = a.x;  As[lc + 1][lr] = a.y;  As[lc + 2][lr] = a.z;  As[lc + 3][lr] = a.w;
        Bs[lc + 0][lr] = b4.x; Bs[lc + 1][lr] = b4.y; Bs[lc + 2][lr] = b4.z; Bs[lc + 3][lr] = b4.w;
        __syncthreads();
        #pragma unroll
        for (int kk = 0; kk < BKK; kk++) {
            float4 av = *(const float4*)&As[kk][ty << 2];
            float4 bv = *(const float4*)&Bs[kk][tx << 2];
            float am[4] = {av.x, av.y, av.z, av.w};
            float bn[4] = {bv.x, bv.y, bv.z, bv.w};
            #pragma unroll
            for (int i = 0; i < 4; i++)
                #pragma unroll
                for (int j = 0; j < 4; j++)
                    acc[i][j] += am[i] * bn[j];
        }
        __syncthreads();
    }
    #pragma unroll
    for (int i = 0; i < 4; i++) {
        int gi = i0 + (ty << 2) + i;
        int gj = j0 + (tx << 2);
        float4 out;
        out.x = (gj + 0 <= gi) ? acc[i][0] * scale : NEG_INF;
        out.y = (gj + 1 <= gi) ? acc[i][1] * scale : NEG_INF;
        out.z = (gj + 2 <= gi) ? acc[i][2] * scale : NEG_INF;
        out.w = (gj + 3 <= gi) ? acc[i][3] * scale : NEG_INF;
        *(float4*)(Out + (size_t)gi * Sn + gj) = out;
    }
}

// ---------------------------------------------------------------------------
// Row softmax over valid prefix [0, i]; writes exact zeros for j>i.
// (exp(-1e7 - m) == 0.0f in fp32, matching the reference exactly.)
// ---------------------------------------------------------------------------
__global__ __launch_bounds__(256) void softmax_kernel(float* wts, int use_fallback)
{
    float* __restrict__ Wt = use_fallback ? scratch_W() : wts;
    const int r = blockIdx.x;         // 0 .. B*S-1
    const int b = r >> 12;            // / Sn
    const int i = r & (Sn - 1);
    float* row = Wt + (size_t)b * Sn * Sn + (size_t)i * Sn;
    const int L = i + 1;
    const int tid = threadIdx.x;
    __shared__ float red[256];

    float m = -1e30f;
    for (int j = tid; j < L; j += 256) m = fmaxf(m, row[j]);
    red[tid] = m; __syncthreads();
    for (int s = 128; s > 0; s >>= 1) {
        if (tid < s) red[tid] = fmaxf(red[tid], red[tid + s]);
        __syncthreads();
    }
    m = red[0]; __syncthreads();

    float sum = 0.f;
    for (int j = tid; j < L; j += 256) sum += __expf(row[j] - m);
    red[tid] = sum; __syncthreads();
    for (int s = 128; s > 0; s >>= 1) {
        if (tid < s) red[tid] += red[tid + s];
        __syncthreads();
    }
    const float inv = 1.f / red[0];

    for (int j = tid; j < Sn; j += 256) {
        float v = (j < L) ? __expf(row[j] - m) * inv : 0.f;
        row[j] = v;
    }
}

// ---------------------------------------------------------------------------
// PV: C[b,i,h] = sum_j W[b,i,j] V[b,j,h]; k-loop limited to j < i0+BLK (causal:
// weights are exactly 0 beyond the diagonal after softmax).
// ---------------------------------------------------------------------------
__global__ __launch_bounds__(256) void pv_kernel(
    float* wts, int use_fallback, float* __restrict__ Cout)
{
    const float* __restrict__ Wt = use_fallback ? scratch_W() : wts;
    const int b = blockIdx.z;
    const int i0 = blockIdx.y * BLK;
    const int n0 = blockIdx.x * BLK;
    const float* A  = Wt + (size_t)b * Sn * Sn;
    const float* Bm = scratch_V() + (size_t)b * Sn * Hn;
    float* Out = Cout + (size_t)b * Sn * Hn;
    const int kmax = i0 + BLK;

    __shared__ float As[BKK][BLK];
    __shared__ float Bs[BKK][BLK];
    const int tid = threadIdx.x;
    const int tx = tid & 15, ty = tid >> 4;
    const int lr = tid >> 2;         // A-tile row 0..63
    const int lc = (tid & 3) << 2;   // A-tile col 0..12
    const int br = tid >> 4;         // B-tile row 0..15
    const int bc = (tid & 15) << 2;  // B-tile col 0..60

    float acc[4][4] = {};
    for (int k0 = 0; k0 < kmax; k0 += BKK) {
        float4 a = *(const float4*)(A + (size_t)(i0 + lr) * Sn + k0 + lc);
        As[lc + 0][lr] = a.x; As[lc + 1][lr] = a.y; As[lc + 2][lr] = a.z; As[lc + 3][lr] = a.w;
        float4 b4 = *(const float4*)(Bm + (size_t)(k0 + br) * Hn + n0 + bc);
        *(float4*)&Bs[br][bc] = b4;
        __syncthreads();
        #pragma unroll
        for (int kk = 0; kk < BKK; kk++) {
            float4 av = *(const float4*)&As[kk][ty << 2];
            float4 bv = *(const float4*)&Bs[kk][tx << 2];
            float am[4] = {av.x, av.y, av.z, av.w};
            float bn[4] = {bv.x, bv.y, bv.z, bv.w};
            #pragma unroll
            for (int i = 0; i < 4; i++)
                #pragma unroll
                for (int j = 0; j < 4; j++)
                    acc[i][j] += am[i] * bn[j];
        }
        __syncthreads();
    }
    #pragma unroll
    for (int i = 0; i < 4; i++) {
        int gi = i0 + (ty << 2) + i;
        int gn = n0 + (tx << 2);
        float4 out = {acc[i][0], acc[i][1], acc[i][2], acc[i][3]};
        *(float4*)(Out + (size_t)gi * Hn + gn) = out;
    }
}

// ---------------------------------------------------------------------------
// kernel_launch: ONLY kernel launches (graph-capture safe; no runtime APIs).
// ---------------------------------------------------------------------------
extern "C" void kernel_launch(void* const* d_in, const int* in_sizes, int n_in,
                              void* d_out, int out_size)
{
    const float* queries = (const float*)d_in[0];
    const float* keys    = (const float*)d_in[1];
    const float* values  = (const float*)d_in[2];
    const float* Wq = (const float*)d_in[3];
    const float* bq = (const float*)d_in[4];
    const float* Wk = (const float*)d_in[5];
    const float* bk = (const float*)d_in[6];
    const float* Wv = (const float*)d_in[7];
    const float* bv = (const float*)d_in[8];

    float* ctx = (float*)d_out;
    const size_t ctx_elems = QKV_ELEMS;              // 8388608 (B*S*H)
    // If the harness output holds both tensors (context, weights), write weights
    // directly into d_out; otherwise use the device-global fallback region.
    const int use_fallback = ((size_t)out_size >= ctx_elems + W_ELEMS) ? 0 : 1;
    float* wts = use_fallback ? (float*)nullptr : (ctx + ctx_elems);

    const int M = Bn * Sn;  // 16384 tokens
    dim3 blk(256);

    // 1) Projections
    dim3 gproj(Hn / BLK, M / BLK);
    proj_kernel<<<gproj, blk>>>(queries, Wq, bq, 0);
    proj_kernel<<<gproj, blk>>>(keys,    Wk, bk, 1);
    proj_kernel<<<gproj, blk>>>(values,  Wv, bv, 2);

    // 2) Scores with causal mask
    const float scale = 0.044194173824159216f;  // 1/sqrt(512)
    dim3 gsc(Sn / BLK, Sn / BLK, Bn);
    scores_kernel<<<gsc, blk>>>(wts, use_fallback, scale);

    // 3) Row softmax (writes zeros above diagonal)
    softmax_kernel<<<Bn * Sn, blk>>>(wts, use_fallback);

    // 4) Context = weights @ V (causal k-limit)
    dim3 gpv(Hn / BLK, Sn / BLK, Bn);
    pv_kernel<<<gpv, blk>>>(wts, use_fallback, ctx);
}

// round 4
// speedup vs baseline: 2.8535x; 2.8535x over previous
#include <cuda_runtime.h>
#include <cstdint>
#include <cstddef>

// Problem constants
#define Bn 4
#define Sn 4096
#define Hn 512

// GEMM tiling
#define BM 128
#define BN 128
#define BK 32
#define LDA 36    // padded smem stride for [128][32] tiles (floats); 36*4=144 B, 16B aligned
#define LDB2 132  // padded smem stride for [32][128] V tile; 132*4=528 B, 16B aligned

// Scratch (allocation forbidden -> one __device__ global).
// Layout: [Q][K][V] each B*S*H, then weights fallback B*S*S.
#define QKV_ELEMS ((size_t)Bn * Sn * Hn)   // 8388608
#define W_ELEMS   ((size_t)Bn * Sn * Sn)   // 67108864
__device__ float g_scratch[3 * QKV_ELEMS + W_ELEMS];

__device__ __forceinline__ float* scratch_Q() { return g_scratch; }
__device__ __forceinline__ float* scratch_K() { return g_scratch + QKV_ELEMS; }
__device__ __forceinline__ float* scratch_V() { return g_scratch + 2 * QKV_ELEMS; }
__device__ __forceinline__ float* scratch_W() { return g_scratch + 3 * QKV_ELEMS; }

// Round fp32 -> tf32 (round-to-nearest) ; result is a b32 bit pattern.
__device__ __forceinline__ uint32_t f2tf32(float x) {
    uint32_t o;
    asm("cvt.rna.tf32.f32 %0, %1;" : "=r"(o) : "f"(x));
    return o;
}

#define MMA_TF32(d, a, b0, b1)                                               \
    asm volatile(                                                            \
        "mma.sync.aligned.m16n8k8.row.col.f32.tf32.tf32.f32 "                \
        "{%0,%1,%2,%3}, {%4,%5,%6,%7}, {%8,%9}, {%0,%1,%2,%3};"              \
        : "+f"((d)[0]), "+f"((d)[1]), "+f"((d)[2]), "+f"((d)[3])             \
        : "r"((a)[0]), "r"((a)[1]), "r"((a)[2]), "r"((a)[3]),                \
          "r"(b0), "r"(b1))

// Load a 128x32 fp32 tile (row stride = gstride) into smem (stride LDA),
// rounding to tf32. 256 threads.
__device__ __forceinline__ void load_tile_128x32(
    uint32_t* __restrict__ smem, const float* __restrict__ src, int gstride, int tid)
{
    const int lr = tid >> 3;          // 0..31
    const int lc = (tid & 7) << 2;    // 0,4,...,28
    #pragma unroll
    for (int p = 0; p < 4; p++) {
        int row = p * 32 + lr;
        float4 v = *(const float4*)(src + (size_t)row * gstride + lc);
        uint4 u = {f2tf32(v.x), f2tf32(v.y), f2tf32(v.z), f2tf32(v.w)};
        *(uint4*)(&smem[row * LDA + lc]) = u;
    }
}

// ---------------------------------------------------------------------------
// NT GEMM warp-tile core: acc += As(128xBK, row-major) x Bs(128xBK, row-major)^T
// Warp w computes rows [32*(w%4), +32) x cols [64*(w/4), +64).
// ---------------------------------------------------------------------------
__device__ __forceinline__ void warptile_nt(
    const uint32_t* __restrict__ As, const uint32_t* __restrict__ Bs,
    float acc[2][8][4], int wm, int wn, int gid, int tig)
{
    #pragma unroll
    for (int kk = 0; kk < 4; kk++) {
        const int kb = kk * 8;
        uint32_t a[2][4];
        #pragma unroll
        for (int mi = 0; mi < 2; mi++) {
            int r0 = wm + mi * 16 + gid;
            a[mi][0] = As[(r0)     * LDA + kb + tig];
            a[mi][1] = As[(r0 + 8) * LDA + kb + tig];
            a[mi][2] = As[(r0)     * LDA + kb + tig + 4];
            a[mi][3] = As[(r0 + 8) * LDA + kb + tig + 4];
        }
        #pragma unroll
        for (int ni = 0; ni < 8; ni++) {
            int c0 = wn + ni * 8 + gid;
            uint32_t b0 = Bs[c0 * LDA + kb + tig];
            uint32_t b1 = Bs[c0 * LDA + kb + tig + 4];
            #pragma unroll
            for (int mi = 0; mi < 2; mi++) MMA_TF32(acc[mi][ni], a[mi], b0, b1);
        }
    }
}

// ---------------------------------------------------------------------------
// Projection: C[m,n] = sum_k A[m,k]*W[n,k] + bias[n].  M=16384,N=512,K=512.
// dst_sel: 0->Q, 1->K, 2->V.  Grid (N/BN, M/BM), 256 threads.
// ---------------------------------------------------------------------------
__global__ __launch_bounds__(256) void proj_tc(
    const float* __restrict__ A, const float* __restrict__ W,
    const float* __restrict__ bias, int dst_sel)
{
    float* __restrict__ C =
        (dst_sel == 0) ? scratch_Q() : (dst_sel == 1) ? scratch_K() : scratch_V();

    __shared__ __align__(16) uint32_t As[BM * LDA];
    __shared__ __align__(16) uint32_t Bs[BN * LDA];

    const int tid = threadIdx.x;
    const int warp = tid >> 5, lane = tid & 31;
    const int gid = lane >> 2, tig = lane & 3;
    const int wm = (warp & 3) * 32, wn = (warp >> 2) * 64;
    const int m0 = blockIdx.y * BM, n0 = blockIdx.x * BN;

    float acc[2][8][4] = {};
    for (int k0 = 0; k0 < Hn; k0 += BK) {
        load_tile_128x32(As, A + (size_t)m0 * Hn + k0, Hn, tid);
        load_tile_128x32(Bs, W + (size_t)n0 * Hn + k0, Hn, tid);
        __syncthreads();
        warptile_nt(As, Bs, acc, wm, wn, gid, tig);
        __syncthreads();
    }

    #pragma unroll
    for (int ni = 0; ni < 8; ni++) {
        int col = n0 + wn + ni * 8 + 2 * tig;
        float b0 = bias[col], b1 = bias[col + 1];
        #pragma unroll
        for (int mi = 0; mi < 2; mi++) {
            int r0 = m0 + wm + mi * 16 + gid;
            float2 v0 = {acc[mi][ni][0] + b0, acc[mi][ni][1] + b1};
            float2 v1 = {acc[mi][ni][2] + b0, acc[mi][ni][3] + b1};
            *(float2*)(C + (size_t)r0 * Hn + col) = v0;
            *(float2*)(C + (size_t)(r0 + 8) * Hn + col) = v1;
        }
    }
}

// ---------------------------------------------------------------------------
// Scores: W[b,i,j] = scale * sum_h Q[b,i,h]*K[b,j,h] for lower-tri blocks.
// Entries with j>i are left unwritten — softmax zero-fills them.
// Grid (S/BN, S/BM, B); skip blocks fully above the diagonal.
// ---------------------------------------------------------------------------
__global__ __launch_bounds__(256) void scores_tc(
    float* wts, int use_fallback, float scale)
{
    const int bx = blockIdx.x, by = blockIdx.y, b = blockIdx.z;
    if (bx > by) return;  // block fully above diagonal (j0 >= i0 + BM)

    float* __restrict__ Wout = (use_fallback ? scratch_W() : wts) + (size_t)b * Sn * Sn;
    const float* Qp = scratch_Q() + (size_t)b * Sn * Hn;
    const float* Kp = scratch_K() + (size_t)b * Sn * Hn;
    const int i0 = by * BM, j0 = bx * BN;

    __shared__ __align__(16) uint32_t As[BM * LDA];
    __shared__ __align__(16) uint32_t Bs[BN * LDA];

    const int tid = threadIdx.x;
    const int warp = tid >> 5, lane = tid & 31;
    const int gid = lane >> 2, tig = lane & 3;
    const int wm = (warp & 3) * 32, wn = (warp >> 2) * 64;

    float acc[2][8][4] = {};
    for (int k0 = 0; k0 < Hn; k0 += BK) {
        load_tile_128x32(As, Qp + (size_t)i0 * Hn + k0, Hn, tid);
        load_tile_128x32(Bs, Kp + (size_t)j0 * Hn + k0, Hn, tid);
        __syncthreads();
        warptile_nt(As, Bs, acc, wm, wn, gid, tig);
        __syncthreads();
    }

    #pragma unroll
    for (int ni = 0; ni < 8; ni++) {
        int col = j0 + wn + ni * 8 + 2 * tig;
        #pragma unroll
        for (int mi = 0; mi < 2; mi++) {
            int r0 = i0 + wm + mi * 16 + gid;
            float2 v0 = {acc[mi][ni][0] * scale, acc[mi][ni][1] * scale};
            float2 v1 = {acc[mi][ni][2] * scale, acc[mi][ni][3] * scale};
            *(float2*)(Wout + (size_t)r0 * Sn + col) = v0;
            *(float2*)(Wout + (size_t)(r0 + 8) * Sn + col) = v1;
        }
    }
}

// ---------------------------------------------------------------------------
// Row softmax over valid prefix [0,i]; zero-fills j>i (incl. unwritten blocks).
// ---------------------------------------------------------------------------
__global__ __launch_bounds__(256) void softmax_kernel(float* wts, int use_fallback)
{
    float* __restrict__ Wt = use_fallback ? scratch_W() : wts;
    const int r = blockIdx.x;
    const int b = r >> 12;
    const int i = r & (Sn - 1);
    float* row = Wt + (size_t)b * Sn * Sn + (size_t)i * Sn;
    const int L = i + 1;
    const int tid = threadIdx.x;
    __shared__ float red[256];

    float m = -1e30f;
    for (int j = tid; j < L; j += 256) m = fmaxf(m, row[j]);
    red[tid] = m; __syncthreads();
    for (int s = 128; s > 0; s >>= 1) {
        if (tid < s) red[tid] = fmaxf(red[tid], red[tid + s]);
        __syncthreads();
    }
    m = red[0]; __syncthreads();

    float sum = 0.f;
    for (int j = tid; j < L; j += 256) sum += __expf(row[j] - m);
    red[tid] = sum; __syncthreads();
    for (int s = 128; s > 0; s >>= 1) {
        if (tid < s) red[tid] += red[tid + s];
        __syncthreads();
    }
    const float inv = 1.f / red[0];

    for (int j = tid; j < Sn; j += 256) {
        float v = (j < L) ? __expf(row[j] - m) * inv : 0.f;
        row[j] = v;
    }
}

// ---------------------------------------------------------------------------
// PV: C[b,i,h] = sum_j W[b,i,j]*V[b,j,h]; k-loop limited to j < i0+BM.
// A = weights (row-major, NN), B = V[k][n] (row-major in n).
// Grid (H/BN, S/BM, B).
// ---------------------------------------------------------------------------
__global__ __launch_bounds__(256) void pv_tc(
    float* wts, int use_fallback, float* __restrict__ Cout)
{
    const int b = blockIdx.z;
    const int i0 = blockIdx.y * BM, n0 = blockIdx.x * BN;
    const float* __restrict__ Wt =
        (use_fallback ? scratch_W() : wts) + (size_t)b * Sn * Sn;
    const float* __restrict__ Vp = scratch_V() + (size_t)b * Sn * Hn;
    float* __restrict__ Out = Cout + (size_t)b * Sn * Hn;
    const int kmax = i0 + BM;  // weights exactly 0 beyond diagonal

    __shared__ __align__(16) uint32_t As[BM * LDA];    // weights tile 128xBK
    __shared__ __align__(16) uint32_t Bs[BK * LDB2];   // V tile BKx128

    const int tid = threadIdx.x;
    const int warp = tid >> 5, lane = tid & 31;
    const int gid = lane >> 2, tig = lane & 3;
    const int wm = (warp & 3) * 32, wn = (warp >> 2) * 64;

    // V-tile loader indices: 32 rows x 128 cols
    const int vr = tid >> 5;          // 0..7
    const int vc = (tid & 31) << 2;   // 0..124

    float acc[2][8][4] = {};
    for (int k0 = 0; k0 < kmax; k0 += BK) {
        load_tile_128x32(As, Wt + (size_t)i0 * Sn + k0, Sn, tid);
        #pragma unroll
        for (int p = 0; p < 4; p++) {
            int row = p * 8 + vr;
            float4 v = *(const float4*)(Vp + (size_t)(k0 + row) * Hn + n0 + vc);
            uint4 u = {f2tf32(v.x), f2tf32(v.y), f2tf32(v.z), f2tf32(v.w)};
            *(uint4*)(&Bs[row * LDB2 + vc]) = u;
        }
        __syncthreads();

        #pragma unroll
        for (int kk = 0; kk < 4; kk++) {
            const int kb = kk * 8;
            uint32_t a[2][4];
            #pragma unroll
            for (int mi = 0; mi < 2; mi++) {
                int r0 = wm + mi * 16 + gid;
                a[mi][0] = As[(r0)     * LDA + kb + tig];
                a[mi][1] = As[(r0 + 8) * LDA + kb + tig];
                a[mi][2] = As[(r0)     * LDA + kb + tig + 4];
                a[mi][3] = As[(r0 + 8) * LDA + kb + tig + 4];
            }
            #pragma unroll
            for (int ni = 0; ni < 8; ni++) {
                int c0 = wn + ni * 8 + gid;
                uint32_t b0 = Bs[(kb + tig)     * LDB2 + c0];
                uint32_t b1 = Bs[(kb + tig + 4) * LDB2 + c0];
                #pragma unroll
                for (int mi = 0; mi < 2; mi++) MMA_TF32(acc[mi][ni], a[mi], b0, b1);
            }
        }
        __syncthreads();
    }

    #pragma unroll
    for (int ni = 0; ni < 8; ni++) {
        int col = n0 + wn + ni * 8 + 2 * tig;
        #pragma unroll
        for (int mi = 0; mi < 2; mi++) {
            int r0 = i0 + wm + mi * 16 + gid;
            float2 v0 = {acc[mi][ni][0], acc[mi][ni][1]};
            float2 v1 = {acc[mi][ni][2], acc[mi][ni][3]};
            *(float2*)(Out + (size_t)r0 * Hn + col) = v0;
            *(float2*)(Out + (size_t)(r0 + 8) * Hn + col) = v1;
        }
    }
}

// ---------------------------------------------------------------------------
// kernel_launch: ONLY kernel launches (graph-capture safe).
// ---------------------------------------------------------------------------
extern "C" void kernel_launch(void* const* d_in, const int* in_sizes, int n_in,
                              void* d_out, int out_size)
{
    const float* queries = (const float*)d_in[0];
    const float* keys    = (const float*)d_in[1];
    const float* values  = (const float*)d_in[2];
    const float* Wq = (const float*)d_in[3];
    const float* bq = (const float*)d_in[4];
    const float* Wk = (const float*)d_in[5];
    const float* bk = (const float*)d_in[6];
    const float* Wv = (const float*)d_in[7];
    const float* bv = (const float*)d_in[8];

    float* ctx = (float*)d_out;
    const size_t ctx_elems = QKV_ELEMS;
    const int use_fallback = ((size_t)out_size >= ctx_elems + W_ELEMS) ? 0 : 1;
    float* wts = use_fallback ? (float*)nullptr : (ctx + ctx_elems);

    const int M = Bn * Sn;  // 16384
    dim3 blk(256);

    // 1) Projections (tf32 TC)
    dim3 gproj(Hn / BN, M / BM);
    proj_tc<<<gproj, blk>>>(queries, Wq, bq, 0);
    proj_tc<<<gproj, blk>>>(keys,    Wk, bk, 1);
    proj_tc<<<gproj, blk>>>(values,  Wv, bv, 2);

    // 2) Scores (tf32 TC, causal block skip; masked entries left for softmax)
    const float scale = 0.044194173824159216f;  // 1/sqrt(512)
    dim3 gsc(Sn / BN, Sn / BM, Bn);
    scores_tc<<<gsc, blk>>>(wts, use_fallback, scale);

    // 3) Row softmax (writes zeros above diagonal)
    softmax_kernel<<<Bn * Sn, blk>>>(wts, use_fallback);

    // 4) Context = weights @ V (tf32 TC, causal k-limit)
    dim3 gpv(Hn / BN, Sn / BM, Bn);
    pv_tc<<<gpv, blk>>>(wts, use_fallback, ctx);
}